// round 2
// baseline (speedup 1.0000x reference)
#include <cuda_runtime.h>

// ---------------- problem constants ----------------
#define SLEN 64
#define TLEN 64
#define BATCH 64
#define EDIM 256
#define HDIM 512
#define G4 2048           // 4*H
#define OUTV 6000
#define DSTEPS 63         // TLEN-1

// ---------------- static device scratch ----------------
__device__ float g_Xenc[SLEN * BATCH * G4];       // precomputed emb@Wih0^T (encoder)
__device__ float g_Xdec[DSTEPS * BATCH * G4];     // precomputed emb@Wih0[:, :E]^T (decoder)
__device__ float g_embS[SLEN * BATCH * EDIM];
__device__ float g_embT[DSTEPS * BATCH * EDIM];
__device__ float g_encouts[SLEN * BATCH * HDIM];  // encoder h1 per step
__device__ float g_dech1[DSTEPS * BATCH * HDIM];  // decoder h1 per step
__device__ float g_gpart[8 * BATCH * G4];         // K-split partial gates
__device__ float g_Wenc1[G4 * 1024];              // [enc_Wih1 | enc_Whh1]
__device__ float g_Wdec0[G4 * 1024];              // [dec_Wih0[:,E:] | dec_Whh0]
__device__ float g_Wdec1[G4 * 1024];              // [dec_Wih1 | dec_Whh1]
__device__ float g_encA1[BATCH * 1024];           // [h0_enc | h1_enc]
__device__ float g_decA0[BATCH * 1024];           // [weighted | h0_dec]
__device__ float g_decA1[BATCH * 1024];           // [h0_dec | h1_dec]
__device__ float g_c0[BATCH * HDIM];
__device__ float g_c1[BATCH * HDIM];

static __device__ __forceinline__ float sigmf(float x) {
    return 1.0f / (1.0f + __expf(-x));
}

// ---------------- utility: zero a region ----------------
__global__ void zero_kernel(float* __restrict__ p, int n) {
    int i = blockIdx.x * blockDim.x + threadIdx.x;
    if (i < n) p[i] = 0.0f;
}

// ---------------- pack concatenated weight matrices ----------------
__global__ void pack_weights(const float* __restrict__ eWih1, const float* __restrict__ eWhh1,
                             const float* __restrict__ dWih0, const float* __restrict__ dWhh0,
                             const float* __restrict__ dWih1, const float* __restrict__ dWhh1) {
    int idx = blockIdx.x * 256 + threadIdx.x;  // < 2048*1024
    int r = idx >> 10;
    int c = idx & 1023;
    if (c < 512) {
        g_Wenc1[idx] = eWih1[r * 512 + c];
        g_Wdec0[idx] = dWih0[r * 768 + 256 + c];  // cols E..E+H of dec_Wih0
        g_Wdec1[idx] = dWih1[r * 512 + c];
    } else {
        g_Wenc1[idx] = eWhh1[r * 512 + c - 512];
        g_Wdec0[idx] = dWhh0[r * 512 + c - 512];
        g_Wdec1[idx] = dWhh1[r * 512 + c - 512];
    }
}

// ---------------- gather embeddings for all timesteps ----------------
__global__ void gather_embed(const int* __restrict__ src, const int* __restrict__ trg,
                             const float* __restrict__ enc_emb, const float* __restrict__ dec_emb) {
    int row = blockIdx.x;           // 0..(4096+4032-1)
    int t4 = threadIdx.x;           // 64 threads; each copies one float4 (256 floats/row)
    if (row < SLEN * BATCH) {
        int tok = src[row];
        reinterpret_cast<float4*>(g_embS + row * EDIM)[t4] =
            reinterpret_cast<const float4*>(enc_emb + (long)tok * EDIM)[t4];
    } else {
        int r = row - SLEN * BATCH;
        int tok = trg[r];
        reinterpret_cast<float4*>(g_embT + r * EDIM)[t4] =
            reinterpret_cast<const float4*>(dec_emb + (long)tok * EDIM)[t4];
    }
}

// ---------------- big GEMM: C[M,N] = A[M,K] @ W[N,K]^T (+bias) ----------------
// tile 128x128, 256 threads, 8x8 per thread
__global__ void big_gemm(const float* __restrict__ A, int lda,
                         const float* __restrict__ W, int ldw,
                         const float* __restrict__ bias,
                         float* __restrict__ C, int ldc,
                         int M, int N, int K) {
    __shared__ __align__(16) float Ash[16][132];
    __shared__ __align__(16) float Wsh[16][132];
    int row0 = blockIdx.y * 128;
    int col0 = blockIdx.x * 128;
    int tid = threadIdx.x;
    int tx = tid & 15, ty = tid >> 4;
    int lr = tid >> 2;          // 0..63
    int lk4 = (tid & 3) * 4;    // 0,4,8,12

    float acc[8][8];
#pragma unroll
    for (int i = 0; i < 8; i++)
#pragma unroll
        for (int j = 0; j < 8; j++) acc[i][j] = 0.0f;

    for (int kb = 0; kb < K; kb += 16) {
#pragma unroll
        for (int h = 0; h < 2; h++) {
            int rr = lr + h * 64;
            int r = row0 + rr;
            float4 av = make_float4(0.f, 0.f, 0.f, 0.f);
            if (r < M) av = *reinterpret_cast<const float4*>(&A[(long)r * lda + kb + lk4]);
            Ash[lk4 + 0][rr] = av.x; Ash[lk4 + 1][rr] = av.y;
            Ash[lk4 + 2][rr] = av.z; Ash[lk4 + 3][rr] = av.w;
            int c = col0 + rr;
            float4 wv = make_float4(0.f, 0.f, 0.f, 0.f);
            if (c < N) wv = *reinterpret_cast<const float4*>(&W[(long)c * ldw + kb + lk4]);
            Wsh[lk4 + 0][rr] = wv.x; Wsh[lk4 + 1][rr] = wv.y;
            Wsh[lk4 + 2][rr] = wv.z; Wsh[lk4 + 3][rr] = wv.w;
        }
        __syncthreads();
#pragma unroll
        for (int kk = 0; kk < 16; kk++) {
            float a[8], w[8];
            float4 a0 = *reinterpret_cast<float4*>(&Ash[kk][ty * 8]);
            float4 a1 = *reinterpret_cast<float4*>(&Ash[kk][ty * 8 + 4]);
            float4 w0 = *reinterpret_cast<float4*>(&Wsh[kk][tx * 8]);
            float4 w1 = *reinterpret_cast<float4*>(&Wsh[kk][tx * 8 + 4]);
            a[0] = a0.x; a[1] = a0.y; a[2] = a0.z; a[3] = a0.w;
            a[4] = a1.x; a[5] = a1.y; a[6] = a1.z; a[7] = a1.w;
            w[0] = w0.x; w[1] = w0.y; w[2] = w0.z; w[3] = w0.w;
            w[4] = w1.x; w[5] = w1.y; w[6] = w1.z; w[7] = w1.w;
#pragma unroll
            for (int i = 0; i < 8; i++)
#pragma unroll
                for (int j = 0; j < 8; j++) acc[i][j] += a[i] * w[j];
        }
        __syncthreads();
    }
#pragma unroll
    for (int i = 0; i < 8; i++) {
        int r = row0 + ty * 8 + i;
        if (r >= M) continue;
#pragma unroll
        for (int j = 0; j < 8; j++) {
            int c = col0 + tx * 8 + j;
            if (c < N) C[(long)r * ldc + c] = acc[i][j] + (bias ? bias[c] : 0.0f);
        }
    }
}

// ---------------- per-step recurrent GEMM with K-split ----------------
// partial[ks][64][2048] = A[64, k0:k0+KC] @ W[2048, k0:k0+KC]^T
// tile 64x64, 256 threads, 4x4 per thread. grid = (32, KS), KC = 128.
__global__ void step_gemm(const float* __restrict__ A, int lda,
                          const float* __restrict__ W, int ldw) {
    __shared__ __align__(16) float Ash[16][68];
    __shared__ __align__(16) float Wsh[16][68];
    int col0 = blockIdx.x * 64;
    int k0 = blockIdx.y * 128;
    int tid = threadIdx.x;
    int tx = tid & 15, ty = tid >> 4;
    int lr = tid >> 2;          // 0..63
    int lk4 = (tid & 3) * 4;

    float acc[4][4];
#pragma unroll
    for (int i = 0; i < 4; i++)
#pragma unroll
        for (int j = 0; j < 4; j++) acc[i][j] = 0.0f;

    for (int kb = 0; kb < 128; kb += 16) {
        float4 av = *reinterpret_cast<const float4*>(&A[lr * lda + k0 + kb + lk4]);
        float4 wv = *reinterpret_cast<const float4*>(&W[(col0 + lr) * ldw + k0 + kb + lk4]);
        Ash[lk4 + 0][lr] = av.x; Ash[lk4 + 1][lr] = av.y;
        Ash[lk4 + 2][lr] = av.z; Ash[lk4 + 3][lr] = av.w;
        Wsh[lk4 + 0][lr] = wv.x; Wsh[lk4 + 1][lr] = wv.y;
        Wsh[lk4 + 2][lr] = wv.z; Wsh[lk4 + 3][lr] = wv.w;
        __syncthreads();
#pragma unroll
        for (int kk = 0; kk < 16; kk++) {
            float4 a = *reinterpret_cast<float4*>(&Ash[kk][ty * 4]);
            float4 w = *reinterpret_cast<float4*>(&Wsh[kk][tx * 4]);
            acc[0][0] += a.x * w.x; acc[0][1] += a.x * w.y; acc[0][2] += a.x * w.z; acc[0][3] += a.x * w.w;
            acc[1][0] += a.y * w.x; acc[1][1] += a.y * w.y; acc[1][2] += a.y * w.z; acc[1][3] += a.y * w.w;
            acc[2][0] += a.z * w.x; acc[2][1] += a.z * w.y; acc[2][2] += a.z * w.z; acc[2][3] += a.z * w.w;
            acc[3][0] += a.w * w.x; acc[3][1] += a.w * w.y; acc[3][2] += a.w * w.z; acc[3][3] += a.w * w.w;
        }
        __syncthreads();
    }
    float* gp = g_gpart + blockIdx.y * (BATCH * G4);
#pragma unroll
    for (int i = 0; i < 4; i++)
#pragma unroll
        for (int j = 0; j < 4; j++)
            gp[(ty * 4 + i) * G4 + col0 + tx * 4 + j] = acc[i][j];
}

// ---------------- LSTM pointwise: reduce K-splits, gate math ----------------
__global__ void lstm_pointwise(int KS, const float* __restrict__ xadd,
                               const float* __restrict__ bih, const float* __restrict__ bhh,
                               float* __restrict__ c,
                               float* __restrict__ hdst1, int s1,
                               float* __restrict__ hdst2, int s2,
                               float* __restrict__ hcopy) {
    int idx = blockIdx.x * 256 + threadIdx.x;  // < 64*512
    int b = idx >> 9;
    int j = idx & 511;
    float g[4];
#pragma unroll
    for (int gi = 0; gi < 4; gi++) {
        int off = b * G4 + gi * 512 + j;
        float v = bih[gi * 512 + j] + bhh[gi * 512 + j];
        if (xadd) v += xadd[off];
        for (int ks = 0; ks < KS; ks++) v += g_gpart[ks * (BATCH * G4) + off];
        g[gi] = v;
    }
    float ig = sigmf(g[0]);
    float fg = sigmf(g[1]);
    float gg = tanhf(g[2]);
    float og = sigmf(g[3]);
    float cn = fg * c[b * 512 + j] + ig * gg;
    c[b * 512 + j] = cn;
    float h = og * tanhf(cn);
    hdst1[b * s1 + j] = h;
    if (hdst2) hdst2[b * s2 + j] = h;
    if (hcopy) hcopy[b * 512 + j] = h;
}

// ---------------- attention: scores -> softmax -> weighted sum ----------------
// one CTA per batch row, 256 threads
__global__ void attn_kernel() {
    int b = blockIdx.x;
    __shared__ float hsh[512];
    __shared__ float ssh[64];
    __shared__ float ash[64];
    int tid = threadIdx.x;
    for (int k = tid; k < 512; k += 256) hsh[k] = g_decA1[b * 1024 + 512 + k];
    __syncthreads();
    int w = tid >> 5, lane = tid & 31;
    for (int s = w; s < 64; s += 8) {
        const float* e = g_encouts + s * (BATCH * HDIM) + b * HDIM;
        float d = 0.0f;
#pragma unroll 4
        for (int k = lane; k < 512; k += 32) d += e[k] * hsh[k];
#pragma unroll
        for (int o = 16; o > 0; o >>= 1) d += __shfl_down_sync(0xffffffffu, d, o);
        if (lane == 0) ssh[s] = d;
    }
    __syncthreads();
    if (tid < 32) {
        float s0 = ssh[tid], s1 = ssh[tid + 32];
        float m = fmaxf(s0, s1);
#pragma unroll
        for (int o = 16; o > 0; o >>= 1) m = fmaxf(m, __shfl_xor_sync(0xffffffffu, m, o));
        float e0 = __expf(s0 - m), e1 = __expf(s1 - m);
        float sum = e0 + e1;
#pragma unroll
        for (int o = 16; o > 0; o >>= 1) sum += __shfl_xor_sync(0xffffffffu, sum, o);
        float inv = 1.0f / sum;
        ash[tid] = e0 * inv;
        ash[tid + 32] = e1 * inv;
    }
    __syncthreads();
    for (int j = tid; j < 512; j += 256) {
        float acc = 0.0f;
#pragma unroll 8
        for (int s = 0; s < 64; s++)
            acc += ash[s] * g_encouts[s * (BATCH * HDIM) + b * HDIM + j];
        g_decA0[b * 1024 + j] = acc;  // weighted context -> first half of decoder L0 input
    }
}

// ---------------- copy encoder final state into decoder state layout ----------------
__global__ void copy_states() {
    int idx = blockIdx.x * 256 + threadIdx.x;  // < 64*512
    int b = idx >> 9;
    int j = idx & 511;
    float h0 = g_encA1[b * 1024 + j];
    float h1 = g_encA1[b * 1024 + 512 + j];
    g_decA0[b * 1024 + 512 + j] = h0;
    g_decA1[b * 1024 + j] = h0;
    g_decA1[b * 1024 + 512 + j] = h1;
}

// ---------------- host ----------------
extern "C" void kernel_launch(void* const* d_in, const int* in_sizes, int n_in,
                              void* d_out, int out_size) {
    const int* src = (const int*)d_in[0];
    const int* trg = (const int*)d_in[1];
    const float* enc_emb  = (const float*)d_in[2];
    const float* eWih0 = (const float*)d_in[3];
    const float* eWhh0 = (const float*)d_in[4];
    const float* ebih0 = (const float*)d_in[5];
    const float* ebhh0 = (const float*)d_in[6];
    const float* eWih1 = (const float*)d_in[7];
    const float* eWhh1 = (const float*)d_in[8];
    const float* ebih1 = (const float*)d_in[9];
    const float* ebhh1 = (const float*)d_in[10];
    const float* dec_emb  = (const float*)d_in[11];
    const float* dWih0 = (const float*)d_in[12];
    const float* dWhh0 = (const float*)d_in[13];
    const float* dbih0 = (const float*)d_in[14];
    const float* dbhh0 = (const float*)d_in[15];
    const float* dWih1 = (const float*)d_in[16];
    const float* dWhh1 = (const float*)d_in[17];
    const float* dbih1 = (const float*)d_in[18];
    const float* dbhh1 = (const float*)d_in[19];
    const float* fcW  = (const float*)d_in[20];
    const float* fcb  = (const float*)d_in[21];
    float* out = (float*)d_out;

    float *Xenc, *Xdec, *embS, *embT, *encouts, *dech1;
    float *encA1, *decA0, *decA1, *c0, *c1;
    cudaGetSymbolAddress((void**)&Xenc, g_Xenc);
    cudaGetSymbolAddress((void**)&Xdec, g_Xdec);
    cudaGetSymbolAddress((void**)&embS, g_embS);
    cudaGetSymbolAddress((void**)&embT, g_embT);
    cudaGetSymbolAddress((void**)&encouts, g_encouts);
    cudaGetSymbolAddress((void**)&dech1, g_dech1);
    cudaGetSymbolAddress((void**)&encA1, g_encA1);
    cudaGetSymbolAddress((void**)&decA0, g_decA0);
    cudaGetSymbolAddress((void**)&decA1, g_decA1);
    cudaGetSymbolAddress((void**)&c0, g_c0);
    cudaGetSymbolAddress((void**)&c1, g_c1);
    float *Wenc1, *Wdec0, *Wdec1;
    cudaGetSymbolAddress((void**)&Wenc1, g_Wenc1);
    cudaGetSymbolAddress((void**)&Wdec0, g_Wdec0);
    cudaGetSymbolAddress((void**)&Wdec1, g_Wdec1);

    // init: zero output row 0 + initial states
    zero_kernel<<<(BATCH * OUTV + 255) / 256, 256>>>(out, BATCH * OUTV);
    zero_kernel<<<(BATCH * 1024 + 255) / 256, 256>>>(encA1, BATCH * 1024);
    zero_kernel<<<(BATCH * HDIM + 255) / 256, 256>>>(c0, BATCH * HDIM);
    zero_kernel<<<(BATCH * HDIM + 255) / 256, 256>>>(c1, BATCH * HDIM);

    pack_weights<<<(G4 * 1024) / 256, 256>>>(eWih1, eWhh1, dWih0, dWhh0, dWih1, dWhh1);
    gather_embed<<<SLEN * BATCH + DSTEPS * BATCH, 64>>>(src, trg, enc_emb, dec_emb);

    // precompute input projections for all timesteps
    big_gemm<<<dim3(16, 32), 256>>>(embS, EDIM, eWih0, EDIM, nullptr,
                                    Xenc, G4, SLEN * BATCH, G4, EDIM);
    big_gemm<<<dim3(16, 32), 256>>>(embT, EDIM, dWih0, 768, nullptr,
                                    Xdec, G4, DSTEPS * BATCH, G4, EDIM);

    // ---- encoder scan ----
    for (int t = 0; t < SLEN; t++) {
        step_gemm<<<dim3(32, 4), 256>>>(encA1, 1024, eWhh0, 512);   // K=512: h0 @ Whh0^T
        lstm_pointwise<<<128, 256>>>(4, Xenc + (long)t * BATCH * G4, ebih0, ebhh0,
                                     c0, encA1, 1024, nullptr, 0, nullptr);
        step_gemm<<<dim3(32, 8), 256>>>(encA1, 1024, Wenc1, 1024);  // K=1024: [h0|h1] @ [Wih1|Whh1]^T
        lstm_pointwise<<<128, 256>>>(8, nullptr, ebih1, ebhh1,
                                     c1, encA1 + 512, 1024, nullptr, 0,
                                     encouts + (long)t * BATCH * HDIM);
    }

    copy_states<<<128, 256>>>();

    // ---- decoder scan (teacher forcing) ----
    for (int t = 0; t < DSTEPS; t++) {
        attn_kernel<<<64, 256>>>();
        step_gemm<<<dim3(32, 8), 256>>>(decA0, 1024, Wdec0, 1024);  // [ctx|h0] @ [Wih0[:,E:]|Whh0]^T
        lstm_pointwise<<<128, 256>>>(8, Xdec + (long)t * BATCH * G4, dbih0, dbhh0,
                                     c0, decA0 + 512, 1024, decA1, 1024, nullptr);
        step_gemm<<<dim3(32, 8), 256>>>(decA1, 1024, Wdec1, 1024);  // [h0|h1] @ [Wih1|Whh1]^T
        lstm_pointwise<<<128, 256>>>(8, nullptr, dbih1, dbhh1,
                                     c1, decA1 + 512, 1024, nullptr, 0,
                                     dech1 + (long)t * BATCH * HDIM);
    }

    // ---- final projection: all decoder outputs at once ----
    big_gemm<<<dim3(47, 32), 256>>>(dech1, HDIM, fcW, HDIM, fcb,
                                    out + (long)BATCH * OUTV, OUTV,
                                    DSTEPS * BATCH, OUTV, HDIM);
}

// round 3
// speedup vs baseline: 1.0148x; 1.0148x over previous
#include <cuda_runtime.h>

// ---------------- problem constants ----------------
#define SLEN 64
#define TLEN 64
#define BATCH 64
#define EDIM 256
#define HDIM 512
#define G4 2048           // 4*H
#define OUTV 6000
#define DSTEPS 63         // TLEN-1

// ---------------- static device scratch ----------------
__device__ float g_Xenc[SLEN * BATCH * G4];       // precomputed emb@Wih0^T (encoder)
__device__ float g_Xdec[DSTEPS * BATCH * G4];     // precomputed emb@Wih0[:, :E]^T (decoder)
__device__ float g_embS[SLEN * BATCH * EDIM];
__device__ float g_embT[DSTEPS * BATCH * EDIM];
__device__ float g_encouts[SLEN * BATCH * HDIM];  // encoder h1 per step
__device__ float g_dech1[DSTEPS * BATCH * HDIM];  // decoder h1 per step
__device__ float g_gpart[8 * BATCH * G4];         // K-split partial gates
__device__ float g_Wenc1[G4 * 1024];              // [enc_Wih1 | enc_Whh1]
__device__ float g_Wdec0[G4 * 1024];              // [dec_Wih0[:,E:] | dec_Whh0]
__device__ float g_Wdec1[G4 * 1024];              // [dec_Wih1 | dec_Whh1]
__device__ float g_encA1[BATCH * 1024];           // [h0_enc | h1_enc]
__device__ float g_decA0[BATCH * 1024];           // [weighted | h0_dec]
__device__ float g_decA1[BATCH * 1024];           // [h0_dec | h1_dec]
__device__ float g_c0[BATCH * HDIM];
__device__ float g_c1[BATCH * HDIM];

static __device__ __forceinline__ float sigmf(float x) {
    return 1.0f / (1.0f + __expf(-x));
}

// ---------------- utility: zero a region ----------------
__global__ void zero_kernel(float* __restrict__ p, int n) {
    int i = blockIdx.x * blockDim.x + threadIdx.x;
    if (i < n) p[i] = 0.0f;
}

// ---------------- pack concatenated weight matrices ----------------
__global__ void pack_weights(const float* __restrict__ eWih1, const float* __restrict__ eWhh1,
                             const float* __restrict__ dWih0, const float* __restrict__ dWhh0,
                             const float* __restrict__ dWih1, const float* __restrict__ dWhh1) {
    int idx = blockIdx.x * 256 + threadIdx.x;  // < 2048*1024
    int r = idx >> 10;
    int c = idx & 1023;
    if (c < 512) {
        g_Wenc1[idx] = eWih1[r * 512 + c];
        g_Wdec0[idx] = dWih0[r * 768 + 256 + c];  // cols E..E+H of dec_Wih0
        g_Wdec1[idx] = dWih1[r * 512 + c];
    } else {
        g_Wenc1[idx] = eWhh1[r * 512 + c - 512];
        g_Wdec0[idx] = dWhh0[r * 512 + c - 512];
        g_Wdec1[idx] = dWhh1[r * 512 + c - 512];
    }
}

// ---------------- gather embeddings for all timesteps ----------------
__global__ void gather_embed(const int* __restrict__ src, const int* __restrict__ trg,
                             const float* __restrict__ enc_emb, const float* __restrict__ dec_emb) {
    int row = blockIdx.x;           // 0..(4096+4032-1)
    int t4 = threadIdx.x;           // 64 threads; each copies one float4 (256 floats/row)
    if (row < SLEN * BATCH) {
        int tok = src[row];
        reinterpret_cast<float4*>(g_embS + row * EDIM)[t4] =
            reinterpret_cast<const float4*>(enc_emb + (long)tok * EDIM)[t4];
    } else {
        int r = row - SLEN * BATCH;
        int tok = trg[r];
        reinterpret_cast<float4*>(g_embT + r * EDIM)[t4] =
            reinterpret_cast<const float4*>(dec_emb + (long)tok * EDIM)[t4];
    }
}

// ---------------- big GEMM: C[M,N] = A[M,K] @ W[N,K]^T (+bias) ----------------
// tile 128x128, 256 threads, 8x8 per thread
__global__ void big_gemm(const float* __restrict__ A, int lda,
                         const float* __restrict__ W, int ldw,
                         const float* __restrict__ bias,
                         float* __restrict__ C, int ldc,
                         int M, int N, int K) {
    __shared__ __align__(16) float Ash[16][132];
    __shared__ __align__(16) float Wsh[16][132];
    int row0 = blockIdx.y * 128;
    int col0 = blockIdx.x * 128;
    int tid = threadIdx.x;
    int tx = tid & 15, ty = tid >> 4;
    int lr = tid >> 2;          // 0..63
    int lk4 = (tid & 3) * 4;    // 0,4,8,12

    float acc[8][8];
#pragma unroll
    for (int i = 0; i < 8; i++)
#pragma unroll
        for (int j = 0; j < 8; j++) acc[i][j] = 0.0f;

    for (int kb = 0; kb < K; kb += 16) {
#pragma unroll
        for (int h = 0; h < 2; h++) {
            int rr = lr + h * 64;
            int r = row0 + rr;
            float4 av = make_float4(0.f, 0.f, 0.f, 0.f);
            if (r < M) av = *reinterpret_cast<const float4*>(&A[(long)r * lda + kb + lk4]);
            Ash[lk4 + 0][rr] = av.x; Ash[lk4 + 1][rr] = av.y;
            Ash[lk4 + 2][rr] = av.z; Ash[lk4 + 3][rr] = av.w;
            int c = col0 + rr;
            float4 wv = make_float4(0.f, 0.f, 0.f, 0.f);
            if (c < N) wv = *reinterpret_cast<const float4*>(&W[(long)c * ldw + kb + lk4]);
            Wsh[lk4 + 0][rr] = wv.x; Wsh[lk4 + 1][rr] = wv.y;
            Wsh[lk4 + 2][rr] = wv.z; Wsh[lk4 + 3][rr] = wv.w;
        }
        __syncthreads();
#pragma unroll
        for (int kk = 0; kk < 16; kk++) {
            float a[8], w[8];
            float4 a0 = *reinterpret_cast<float4*>(&Ash[kk][ty * 8]);
            float4 a1 = *reinterpret_cast<float4*>(&Ash[kk][ty * 8 + 4]);
            float4 w0 = *reinterpret_cast<float4*>(&Wsh[kk][tx * 8]);
            float4 w1 = *reinterpret_cast<float4*>(&Wsh[kk][tx * 8 + 4]);
            a[0] = a0.x; a[1] = a0.y; a[2] = a0.z; a[3] = a0.w;
            a[4] = a1.x; a[5] = a1.y; a[6] = a1.z; a[7] = a1.w;
            w[0] = w0.x; w[1] = w0.y; w[2] = w0.z; w[3] = w0.w;
            w[4] = w1.x; w[5] = w1.y; w[6] = w1.z; w[7] = w1.w;
#pragma unroll
            for (int i = 0; i < 8; i++)
#pragma unroll
                for (int j = 0; j < 8; j++) acc[i][j] += a[i] * w[j];
        }
        __syncthreads();
    }
#pragma unroll
    for (int i = 0; i < 8; i++) {
        int r = row0 + ty * 8 + i;
        if (r >= M) continue;
#pragma unroll
        for (int j = 0; j < 8; j++) {
            int c = col0 + tx * 8 + j;
            if (c < N) C[(long)r * ldc + c] = acc[i][j] + (bias ? bias[c] : 0.0f);
        }
    }
}

// ---------------- per-step recurrent GEMM with K-split ----------------
// partial[ks][64][2048] = A[64, k0:k0+KC] @ W[2048, k0:k0+KC]^T
// tile 64x64, 256 threads, 4x4 per thread. grid = (32, KS), KC = 128.
__global__ void step_gemm(const float* __restrict__ A, int lda,
                          const float* __restrict__ W, int ldw) {
    __shared__ __align__(16) float Ash[16][68];
    __shared__ __align__(16) float Wsh[16][68];
    int col0 = blockIdx.x * 64;
    int k0 = blockIdx.y * 128;
    int tid = threadIdx.x;
    int tx = tid & 15, ty = tid >> 4;
    int lr = tid >> 2;          // 0..63
    int lk4 = (tid & 3) * 4;

    float acc[4][4];
#pragma unroll
    for (int i = 0; i < 4; i++)
#pragma unroll
        for (int j = 0; j < 4; j++) acc[i][j] = 0.0f;

    for (int kb = 0; kb < 128; kb += 16) {
        float4 av = *reinterpret_cast<const float4*>(&A[lr * lda + k0 + kb + lk4]);
        float4 wv = *reinterpret_cast<const float4*>(&W[(col0 + lr) * ldw + k0 + kb + lk4]);
        Ash[lk4 + 0][lr] = av.x; Ash[lk4 + 1][lr] = av.y;
        Ash[lk4 + 2][lr] = av.z; Ash[lk4 + 3][lr] = av.w;
        Wsh[lk4 + 0][lr] = wv.x; Wsh[lk4 + 1][lr] = wv.y;
        Wsh[lk4 + 2][lr] = wv.z; Wsh[lk4 + 3][lr] = wv.w;
        __syncthreads();
#pragma unroll
        for (int kk = 0; kk < 16; kk++) {
            float4 a = *reinterpret_cast<float4*>(&Ash[kk][ty * 4]);
            float4 w = *reinterpret_cast<float4*>(&Wsh[kk][tx * 4]);
            acc[0][0] += a.x * w.x; acc[0][1] += a.x * w.y; acc[0][2] += a.x * w.z; acc[0][3] += a.x * w.w;
            acc[1][0] += a.y * w.x; acc[1][1] += a.y * w.y; acc[1][2] += a.y * w.z; acc[1][3] += a.y * w.w;
            acc[2][0] += a.z * w.x; acc[2][1] += a.z * w.y; acc[2][2] += a.z * w.z; acc[2][3] += a.z * w.w;
            acc[3][0] += a.w * w.x; acc[3][1] += a.w * w.y; acc[3][2] += a.w * w.z; acc[3][3] += a.w * w.w;
        }
        __syncthreads();
    }
    float* gp = g_gpart + blockIdx.y * (BATCH * G4);
#pragma unroll
    for (int i = 0; i < 4; i++)
#pragma unroll
        for (int j = 0; j < 4; j++)
            gp[(ty * 4 + i) * G4 + col0 + tx * 4 + j] = acc[i][j];
}

// ---------------- LSTM pointwise: reduce K-splits, gate math ----------------
__global__ void lstm_pointwise(int KS, const float* __restrict__ xadd,
                               const float* __restrict__ bih, const float* __restrict__ bhh,
                               float* __restrict__ c,
                               float* __restrict__ hdst1, int s1,
                               float* __restrict__ hdst2, int s2,
                               float* __restrict__ hcopy) {
    int idx = blockIdx.x * 256 + threadIdx.x;  // < 64*512
    int b = idx >> 9;
    int j = idx & 511;
    float g[4];
#pragma unroll
    for (int gi = 0; gi < 4; gi++) {
        int off = b * G4 + gi * 512 + j;
        float v = bih[gi * 512 + j] + bhh[gi * 512 + j];
        if (xadd) v += xadd[off];
        for (int ks = 0; ks < KS; ks++) v += g_gpart[ks * (BATCH * G4) + off];
        g[gi] = v;
    }
    float ig = sigmf(g[0]);
    float fg = sigmf(g[1]);
    float gg = tanhf(g[2]);
    float og = sigmf(g[3]);
    float cn = fg * c[b * 512 + j] + ig * gg;
    c[b * 512 + j] = cn;
    float h = og * tanhf(cn);
    hdst1[b * s1 + j] = h;
    if (hdst2) hdst2[b * s2 + j] = h;
    if (hcopy) hcopy[b * 512 + j] = h;
}

// ---------------- attention: scores -> softmax -> weighted sum ----------------
// one CTA per batch row, 256 threads
__global__ void attn_kernel() {
    int b = blockIdx.x;
    __shared__ float hsh[512];
    __shared__ float ssh[64];
    __shared__ float ash[64];
    int tid = threadIdx.x;
    for (int k = tid; k < 512; k += 256) hsh[k] = g_decA1[b * 1024 + 512 + k];
    __syncthreads();
    int w = tid >> 5, lane = tid & 31;
    for (int s = w; s < 64; s += 8) {
        const float* e = g_encouts + s * (BATCH * HDIM) + b * HDIM;
        float d = 0.0f;
#pragma unroll 4
        for (int k = lane; k < 512; k += 32) d += e[k] * hsh[k];
#pragma unroll
        for (int o = 16; o > 0; o >>= 1) d += __shfl_down_sync(0xffffffffu, d, o);
        if (lane == 0) ssh[s] = d;
    }
    __syncthreads();
    if (tid < 32) {
        float s0 = ssh[tid], s1 = ssh[tid + 32];
        float m = fmaxf(s0, s1);
#pragma unroll
        for (int o = 16; o > 0; o >>= 1) m = fmaxf(m, __shfl_xor_sync(0xffffffffu, m, o));
        float e0 = __expf(s0 - m), e1 = __expf(s1 - m);
        float sum = e0 + e1;
#pragma unroll
        for (int o = 16; o > 0; o >>= 1) sum += __shfl_xor_sync(0xffffffffu, sum, o);
        float inv = 1.0f / sum;
        ash[tid] = e0 * inv;
        ash[tid + 32] = e1 * inv;
    }
    __syncthreads();
    for (int j = tid; j < 512; j += 256) {
        float acc = 0.0f;
#pragma unroll 8
        for (int s = 0; s < 64; s++)
            acc += ash[s] * g_encouts[s * (BATCH * HDIM) + b * HDIM + j];
        g_decA0[b * 1024 + j] = acc;  // weighted context -> first half of decoder L0 input
    }
}

// ---------------- copy encoder final state into decoder state layout ----------------
__global__ void copy_states() {
    int idx = blockIdx.x * 256 + threadIdx.x;  // < 64*512
    int b = idx >> 9;
    int j = idx & 511;
    float h0 = g_encA1[b * 1024 + j];
    float h1 = g_encA1[b * 1024 + 512 + j];
    g_decA0[b * 1024 + 512 + j] = h0;
    g_decA1[b * 1024 + j] = h0;
    g_decA1[b * 1024 + 512 + j] = h1;
}

// ---------------- host ----------------
extern "C" void kernel_launch(void* const* d_in, const int* in_sizes, int n_in,
                              void* d_out, int out_size) {
    const int* src = (const int*)d_in[0];
    const int* trg = (const int*)d_in[1];
    const float* enc_emb  = (const float*)d_in[2];
    const float* eWih0 = (const float*)d_in[3];
    const float* eWhh0 = (const float*)d_in[4];
    const float* ebih0 = (const float*)d_in[5];
    const float* ebhh0 = (const float*)d_in[6];
    const float* eWih1 = (const float*)d_in[7];
    const float* eWhh1 = (const float*)d_in[8];
    const float* ebih1 = (const float*)d_in[9];
    const float* ebhh1 = (const float*)d_in[10];
    const float* dec_emb  = (const float*)d_in[11];
    const float* dWih0 = (const float*)d_in[12];
    const float* dWhh0 = (const float*)d_in[13];
    const float* dbih0 = (const float*)d_in[14];
    const float* dbhh0 = (const float*)d_in[15];
    const float* dWih1 = (const float*)d_in[16];
    const float* dWhh1 = (const float*)d_in[17];
    const float* dbih1 = (const float*)d_in[18];
    const float* dbhh1 = (const float*)d_in[19];
    const float* fcW  = (const float*)d_in[20];
    const float* fcb  = (const float*)d_in[21];
    float* out = (float*)d_out;

    float *Xenc, *Xdec, *embS, *embT, *encouts, *dech1;
    float *encA1, *decA0, *decA1, *c0, *c1;
    cudaGetSymbolAddress((void**)&Xenc, g_Xenc);
    cudaGetSymbolAddress((void**)&Xdec, g_Xdec);
    cudaGetSymbolAddress((void**)&embS, g_embS);
    cudaGetSymbolAddress((void**)&embT, g_embT);
    cudaGetSymbolAddress((void**)&encouts, g_encouts);
    cudaGetSymbolAddress((void**)&dech1, g_dech1);
    cudaGetSymbolAddress((void**)&encA1, g_encA1);
    cudaGetSymbolAddress((void**)&decA0, g_decA0);
    cudaGetSymbolAddress((void**)&decA1, g_decA1);
    cudaGetSymbolAddress((void**)&c0, g_c0);
    cudaGetSymbolAddress((void**)&c1, g_c1);
    float *Wenc1, *Wdec0, *Wdec1;
    cudaGetSymbolAddress((void**)&Wenc1, g_Wenc1);
    cudaGetSymbolAddress((void**)&Wdec0, g_Wdec0);
    cudaGetSymbolAddress((void**)&Wdec1, g_Wdec1);

    // init: zero output row 0 + initial states
    zero_kernel<<<(BATCH * OUTV + 255) / 256, 256>>>(out, BATCH * OUTV);
    zero_kernel<<<(BATCH * 1024 + 255) / 256, 256>>>(encA1, BATCH * 1024);
    zero_kernel<<<(BATCH * HDIM + 255) / 256, 256>>>(c0, BATCH * HDIM);
    zero_kernel<<<(BATCH * HDIM + 255) / 256, 256>>>(c1, BATCH * HDIM);

    pack_weights<<<(G4 * 1024) / 256, 256>>>(eWih1, eWhh1, dWih0, dWhh0, dWih1, dWhh1);
    gather_embed<<<SLEN * BATCH + DSTEPS * BATCH, 64>>>(src, trg, enc_emb, dec_emb);

    // precompute input projections for all timesteps
    big_gemm<<<dim3(16, 32), 256>>>(embS, EDIM, eWih0, EDIM, nullptr,
                                    Xenc, G4, SLEN * BATCH, G4, EDIM);
    big_gemm<<<dim3(16, 32), 256>>>(embT, EDIM, dWih0, 768, nullptr,
                                    Xdec, G4, DSTEPS * BATCH, G4, EDIM);

    // ---- encoder scan ----
    for (int t = 0; t < SLEN; t++) {
        step_gemm<<<dim3(32, 4), 256>>>(encA1, 1024, eWhh0, 512);   // K=512: h0 @ Whh0^T
        lstm_pointwise<<<128, 256>>>(4, Xenc + (long)t * BATCH * G4, ebih0, ebhh0,
                                     c0, encA1, 1024, nullptr, 0, nullptr);
        step_gemm<<<dim3(32, 8), 256>>>(encA1, 1024, Wenc1, 1024);  // K=1024: [h0|h1] @ [Wih1|Whh1]^T
        lstm_pointwise<<<128, 256>>>(8, nullptr, ebih1, ebhh1,
                                     c1, encA1 + 512, 1024, nullptr, 0,
                                     encouts + (long)t * BATCH * HDIM);
    }

    copy_states<<<128, 256>>>();

    // ---- decoder scan (teacher forcing) ----
    for (int t = 0; t < DSTEPS; t++) {
        attn_kernel<<<64, 256>>>();
        step_gemm<<<dim3(32, 8), 256>>>(decA0, 1024, Wdec0, 1024);  // [ctx|h0] @ [Wih0[:,E:]|Whh0]^T
        lstm_pointwise<<<128, 256>>>(8, Xdec + (long)t * BATCH * G4, dbih0, dbhh0,
                                     c0, decA0 + 512, 1024, decA1, 1024, nullptr);
        step_gemm<<<dim3(32, 8), 256>>>(decA1, 1024, Wdec1, 1024);  // [h0|h1] @ [Wih1|Whh1]^T
        lstm_pointwise<<<128, 256>>>(8, nullptr, dbih1, dbhh1,
                                     c1, decA1 + 512, 1024, nullptr, 0,
                                     dech1 + (long)t * BATCH * HDIM);
    }

    // ---- final projection: all decoder outputs at once ----
    big_gemm<<<dim3(47, 32), 256>>>(dech1, HDIM, fcW, HDIM, fcb,
                                    out + (long)BATCH * OUTV, OUTV,
                                    DSTEPS * BATCH, OUTV, HDIM);
}